// round 7
// baseline (speedup 1.0000x reference)
#include <cuda_runtime.h>
#include <cstdint>

// DetectionLayer: x (16, 255, 76, 76) f32 -> out (16, 17328, 85) f32
// out[b, a*5776 + gy*76 + gx, c]:
//   c==0: (sigmoid(x0)+gx)*8 ; c==1: (sigmoid(x1)+gy)*8
//   c==2: exp(x2)*aw[a]      ; c==3: exp(x3)*ah[a]
//   c>=4: sigmoid(xc)
// sigmoid(v) = 0.5 + 0.5*tanh(v/2) (1 MUFU). Phase 2 = TMA bulk store.
// Mapping: thread owns 4 consecutive channels x 1 spatial -> coalesced LDG.32,
// conflict-free STS.32 (lane stride 85 words, gcd(85,32)=1).

#define NG    76
#define NGG   (NG * NG)     // 5776
#define NA    3
#define NCH   85
#define NCG   21            // channel quads (84 channels) + 1 tail channel
#define NITEM (NCG * NG)    // 1596 quad-items per block
#define TILE_F (NG * NCH)   // 6460 floats = block's contiguous output chunk
#define TILE_B (TILE_F * 4) // 25840 bytes

__device__ __forceinline__ float tanh_half(float v) {
    float t;
    asm("tanh.approx.f32 %0, %1;" : "=f"(t) : "f"(v * 0.5f));
    return t;  // tanh(v/2); sigmoid(v) = fmaf(t, 0.5f, 0.5f)
}

__global__ __launch_bounds__(256)
void detection_layer_kernel(const float* __restrict__ x, float* __restrict__ out) {
    const int tid = threadIdx.x;
    const int gy = blockIdx.x;   // 0..75
    const int a  = blockIdx.y;   // 0..2
    const int b  = blockIdx.z;   // 0..15

    // smem tile holds the output chunk in FINAL layout: tile[s*85 + c]
    __shared__ __align__(16) float tile[TILE_F];

    const float aw = (a == 0) ? 10.0f : (a == 1 ? 16.0f : 33.0f);
    const float ah = (a == 0) ? 13.0f : (a == 1 ? 30.0f : 23.0f);
    const float ybase = fmaf((float)gy, 8.0f, 4.0f);  // (sig+gy)*8 = 4t + 8gy+4

    // input base for (b, a*85 + 0, gy, 0)
    const float* src = x + ((size_t)(b * (NA * NCH) + a * NCH) * NG + gy) * NG;

    // ---- Phase 1: item i = cg*76 + s ; 4 coalesced LDG.32 + 4 CF STS.32 ----
    {
        int i  = tid;
        int cg = tid / NG;            // one div, once
        int s  = tid - cg * NG;
        #pragma unroll 1
        for (; i < NITEM; i += 256) {
            const float* p = src + (size_t)(cg << 2) * NGG + s;
            const float v0 = p[0];
            const float v1 = p[NGG];
            const float v2 = p[2 * NGG];
            const float v3 = p[3 * NGG];

            float o0, o1, o2, o3;
            if (cg == 0) {
                // c=0: (sig+gx)*8 ; c=1: (sig+gy)*8 ; c=2,3: exp*anchor
                o0 = fmaf(tanh_half(v0), 4.0f, fmaf((float)s, 8.0f, 4.0f));
                o1 = fmaf(tanh_half(v1), 4.0f, ybase);
                o2 = __expf(v2) * aw;
                o3 = __expf(v3) * ah;
            } else {
                o0 = fmaf(tanh_half(v0), 0.5f, 0.5f);
                o1 = fmaf(tanh_half(v1), 0.5f, 0.5f);
                o2 = fmaf(tanh_half(v2), 0.5f, 0.5f);
                o3 = fmaf(tanh_half(v3), 0.5f, 0.5f);
            }
            float* t = &tile[s * NCH + (cg << 2)];
            t[0] = o0; t[1] = o1; t[2] = o2; t[3] = o3;

            // i += 256  ==>  cg += 3, s += 28  (256 = 3*76 + 28)
            cg += 3; s += 28;
            if (s >= NG) { s -= NG; ++cg; }
        }
    }
    // tail channel c = 84 (76 elements, conflict-free stride-85 STS)
    if (tid < NG) {
        const float v = src[(size_t)84 * NGG + tid];
        tile[tid * NCH + 84] = fmaf(tanh_half(v), 0.5f, 0.5f);
    }
    __syncthreads();

    // ---- Phase 2: single TMA bulk store smem -> gmem (25840 B) ----
    if (tid == 0) {
        asm volatile("fence.proxy.async.shared::cta;" ::: "memory");

        uint32_t saddr;
        asm("{ .reg .u64 t; cvta.to.shared.u64 t, %1; cvt.u32.u64 %0, t; }"
            : "=r"(saddr) : "l"(tile));

        float* dst = out +
            ((size_t)b * (NA * NGG) + a * NGG + gy * NG) * (size_t)NCH;

        asm volatile(
            "cp.async.bulk.global.shared::cta.bulk_group [%0], [%1], %2;"
            :: "l"(dst), "r"(saddr), "r"((uint32_t)TILE_B) : "memory");
        asm volatile("cp.async.bulk.commit_group;" ::: "memory");
        asm volatile("cp.async.bulk.wait_group.read 0;" ::: "memory");
    }
}

extern "C" void kernel_launch(void* const* d_in, const int* in_sizes, int n_in,
                              void* d_out, int out_size) {
    const float* x = (const float*)d_in[0];
    float* out = (float*)d_out;
    dim3 grid(NG, NA, 16);
    detection_layer_kernel<<<grid, 256>>>(x, out);
}

// round 8
// speedup vs baseline: 1.0585x; 1.0585x over previous
#include <cuda_runtime.h>
#include <cstdint>

// DetectionLayer: x (16, 255, 76, 76) f32 -> out (16, 17328, 85) f32
// out[b, a*5776 + gy*76 + gx, c]:
//   c==0: (sigmoid(x0)+gx)*8 ; c==1: (sigmoid(x1)+gy)*8
//   c==2: exp(x2)*aw[a]      ; c==3: exp(x3)*ah[a]
//   c>=4: sigmoid(xc)
// sigmoid(v) = 0.5 + 0.5*tanh(v/2) (1 MUFU).
// Block = (b, a, gy pair): reads 608B/channel contiguous, writes one
// 51680B contiguous chunk via a single TMA bulk store.

#define NG     76
#define NGG    (NG * NG)      // 5776
#define NA     3
#define NCH    85
#define NROWS  2              // gy rows per block
#define RV4    (NROWS * NG / 4)   // 38 float4s per channel segment
#define NV4    (NCH * RV4)        // 3230 float4 items per block
#define TILE_F (NROWS * NG * NCH) // 12920 floats
#define TILE_B (TILE_F * 4)       // 51680 bytes
#define NTHR   512

__device__ __forceinline__ float tanh_half(float v) {
    float t;
    asm("tanh.approx.f32 %0, %1;" : "=f"(t) : "f"(v * 0.5f));
    return t;  // tanh(v/2); sigmoid(v) = fmaf(t, 0.5f, 0.5f)
}

__global__ __launch_bounds__(NTHR)
void detection_layer_kernel(const float* __restrict__ x, float* __restrict__ out) {
    extern __shared__ __align__(16) float tile[];  // TILE_F floats, final layout

    const int tid = threadIdx.x;
    const int gy0 = blockIdx.x * NROWS;  // 0,2,..,74
    const int a   = blockIdx.y;          // 0..2
    const int b   = blockIdx.z;          // 0..15

    const float aw = (a == 0) ? 10.0f : (a == 1 ? 16.0f : 33.0f);
    const float ah = (a == 0) ? 13.0f : (a == 1 ? 30.0f : 23.0f);

    // input base for (b, a*85 + 0, gy0, 0); 16B-aligned (gy0 even, 76%4==0)
    const float4* src4 = reinterpret_cast<const float4*>(
        x + ((size_t)(b * (NA * NCH) + a * NCH) * NG + gy0) * NG);

    // ---- Phase 1: item v = c*38 + q ; LDG.128 + 4 scalar STS ----
    {
        int v = tid;
        int c = v / RV4;              // one div, once
        int q = v - c * RV4;          // float4 within 2-row channel segment
        #pragma unroll 1
        while (v < NV4) {
            const float4 in = src4[c * (NGG / 4) + q];

            const int gy_off = q / 19;            // 19 float4s per row
            const int gx0    = (q - gy_off * 19) << 2;

            float o0, o1, o2, o3;
            if (c >= 4) {
                o0 = fmaf(tanh_half(in.x), 0.5f, 0.5f);
                o1 = fmaf(tanh_half(in.y), 0.5f, 0.5f);
                o2 = fmaf(tanh_half(in.z), 0.5f, 0.5f);
                o3 = fmaf(tanh_half(in.w), 0.5f, 0.5f);
            } else if (c == 0) {
                // (sig+gx)*8 = 4*t + 8*gx + 4
                const float base = fmaf((float)gx0, 8.0f, 4.0f);
                o0 = fmaf(tanh_half(in.x), 4.0f, base);
                o1 = fmaf(tanh_half(in.y), 4.0f, base + 8.0f);
                o2 = fmaf(tanh_half(in.z), 4.0f, base + 16.0f);
                o3 = fmaf(tanh_half(in.w), 4.0f, base + 24.0f);
            } else if (c == 1) {
                const float base = fmaf((float)(gy0 + gy_off), 8.0f, 4.0f);
                o0 = fmaf(tanh_half(in.x), 4.0f, base);
                o1 = fmaf(tanh_half(in.y), 4.0f, base);
                o2 = fmaf(tanh_half(in.z), 4.0f, base);
                o3 = fmaf(tanh_half(in.w), 4.0f, base);
            } else {
                const float an = (c == 2) ? aw : ah;
                o0 = __expf(in.x) * an; o1 = __expf(in.y) * an;
                o2 = __expf(in.z) * an; o3 = __expf(in.w) * an;
            }
            float* t = &tile[(gy_off * NG + gx0) * NCH + c];
            t[0]       = o0;
            t[NCH]     = o1;
            t[2 * NCH] = o2;
            t[3 * NCH] = o3;

            // v += 512  ==>  c += 13, q += 18   (512 = 13*38 + 18)
            v += NTHR; c += 13; q += 18;
            if (q >= RV4) { q -= RV4; ++c; }
        }
    }
    __syncthreads();

    // ---- Phase 2: single TMA bulk store smem -> gmem (51680 B) ----
    if (tid == 0) {
        asm volatile("fence.proxy.async.shared::cta;" ::: "memory");

        uint32_t saddr;
        asm("{ .reg .u64 t; cvta.to.shared.u64 t, %1; cvt.u32.u64 %0, t; }"
            : "=r"(saddr) : "l"(tile));

        float* dst = out +
            ((size_t)b * (NA * NGG) + a * NGG + gy0 * NG) * (size_t)NCH;

        asm volatile(
            "cp.async.bulk.global.shared::cta.bulk_group [%0], [%1], %2;"
            :: "l"(dst), "r"(saddr), "r"((uint32_t)TILE_B) : "memory");
        asm volatile("cp.async.bulk.commit_group;" ::: "memory");
        // keep CTA (and its smem) alive until the engine has read the tile
        asm volatile("cp.async.bulk.wait_group.read 0;" ::: "memory");
    }
}

extern "C" void kernel_launch(void* const* d_in, const int* in_sizes, int n_in,
                              void* d_out, int out_size) {
    const float* x = (const float*)d_in[0];
    float* out = (float*)d_out;

    static bool attr_set = false;
    if (!attr_set) {
        cudaFuncSetAttribute(detection_layer_kernel,
                             cudaFuncAttributeMaxDynamicSharedMemorySize,
                             TILE_B);
        attr_set = true;
    }

    dim3 grid(NG / NROWS, NA, 16);
    detection_layer_kernel<<<grid, NTHR, TILE_B>>>(x, out);
}